// round 1
// baseline (speedup 1.0000x reference)
#include <cuda_runtime.h>
#include <cuda_bf16.h>
#include <math.h>
#include <stdint.h>

// ---------------------------------------------------------------------------
// Problem constants
// ---------------------------------------------------------------------------
#define kN   6000
#define kD   128
#define kR   1000
#define kHD  256           // H*D
#define kLR  3             // L+1 sequence length
#define MAXN 0.996f        // 1 - 4e-3
#define CAP  1500000       // CSR capacity per branch (expected nnz ~ 200k)

// ---------------------------------------------------------------------------
// Static device scratch (single pools; carved host-side)
// ---------------------------------------------------------------------------
// float pool layout (element offsets):
//  relagg0 0            (768000)
//  relagg1 768000       (768000)
//  H0      1536000      (768000)
//  H1      2304000      (768000)
//  h1      3072000      (768000)
//  h2      3840000      (768000)
//  es      4608000      (12000)
//  ed      4620000      (12000)
//  seq     4632000      (2304000)
//  q       6936000      (4608000)
//  k       11544000     (4608000)
//  v       16152000     (4608000)
//  oc      20760000     (4608000)
//  fco     25368000     (2304000)
//  t1      27672000     (768000)
//  t2      28440000     (768000)
//  hh      29208000     (768000)
//  bb      29976000     (129)
//  vals0   30000000     (CAP)
//  vals1   31500000     (CAP)
__device__ float g_fpool[33000000];

// int pool layout:
//  rowptr0 0       (6001)
//  rowptr1 6001    (6001)
//  cnt     12002   (6000)
//  cols0   18002   (CAP)
//  cols1   18002+CAP (CAP)
__device__ int g_ipool[18002 + 2 * CAP];

// ---------------------------------------------------------------------------
// Block reductions (blockDim.x == 128)
// ---------------------------------------------------------------------------
__device__ __forceinline__ float brsum128(float v) {
    __shared__ float sh[4];
    #pragma unroll
    for (int o = 16; o > 0; o >>= 1) v += __shfl_down_sync(0xffffffffu, v, o);
    __syncthreads();
    if ((threadIdx.x & 31) == 0) sh[threadIdx.x >> 5] = v;
    __syncthreads();
    return sh[0] + sh[1] + sh[2] + sh[3];
}

__device__ __forceinline__ float brmax128(float v) {
    __shared__ float shm[4];
    #pragma unroll
    for (int o = 16; o > 0; o >>= 1) v = fmaxf(v, __shfl_down_sync(0xffffffffu, v, o));
    __syncthreads();
    if ((threadIdx.x & 31) == 0) shm[threadIdx.x >> 5] = v;
    __syncthreads();
    return fmaxf(fmaxf(shm[0], shm[1]), fmaxf(shm[2], shm[3]));
}

// ---------------------------------------------------------------------------
// CSR build
// ---------------------------------------------------------------------------
__global__ void csr_count(const float* __restrict__ adj, int* __restrict__ cnt) {
    int n = blockIdx.x;
    const float* row = adj + (size_t)n * kN;
    int c = 0;
    for (int m = threadIdx.x; m < kN; m += 128) if (row[m] > 0.f) c++;
    float tot = brsum128((float)c);
    if (threadIdx.x == 0) cnt[n] = (int)(tot + 0.5f);
}

__global__ void scan6000(const int* __restrict__ cnt, int* __restrict__ rowptr) {
    __shared__ int sh[1024];
    int tid = threadIdx.x;
    const int per = 6;
    int base = tid * per;
    int loc[per];
    int s = 0;
    #pragma unroll
    for (int i = 0; i < per; i++) {
        int v = (base + i < kN) ? cnt[base + i] : 0;
        loc[i] = s; s += v;
    }
    sh[tid] = s;
    __syncthreads();
    for (int off = 1; off < 1024; off <<= 1) {
        int v = (tid >= off) ? sh[tid - off] : 0;
        __syncthreads();
        sh[tid] += v;
        __syncthreads();
    }
    int pre = (tid > 0) ? sh[tid - 1] : 0;
    #pragma unroll
    for (int i = 0; i < per; i++) if (base + i < kN) rowptr[base + i] = pre + loc[i];
    if (tid == 1023) rowptr[kN] = sh[1023];
}

__global__ void csr_fill(const float* __restrict__ adj, const int* __restrict__ rowptr,
                         int* __restrict__ cols, float* __restrict__ vals) {
    __shared__ int sh[128];
    int n = blockIdx.x, tid = threadIdx.x;
    const float* row = adj + (size_t)n * kN;
    int c = 0;
    for (int m = tid; m < kN; m += 128) if (row[m] > 0.f) c++;
    sh[tid] = c;
    __syncthreads();
    int off = 0;
    for (int i = 0; i < tid; i++) off += sh[i];
    int pos = rowptr[n] + off;
    for (int m = tid; m < kN; m += 128) {
        float v = row[m];
        if (v > 0.f) { cols[pos] = m; vals[pos] = v; pos++; }
    }
}

// ---------------------------------------------------------------------------
// Relation aggregator: out[n,d] = sum_r radj[n,r]*rel[r,d] / sum_r radj[n,r]
// ---------------------------------------------------------------------------
__global__ void rel_agg_kernel(const float* __restrict__ radj, const float* __restrict__ rel,
                               float* __restrict__ out) {
    int n = blockIdx.x, d = threadIdx.x;
    const float* row = radj + (size_t)n * kR;
    float acc = 0.f, rs = 0.f;
    for (int r = 0; r < kR; r++) {
        float v = row[r];
        if (v != 0.f) { rs += v; acc += v * rel[(size_t)r * kD + d]; }
    }
    out[(size_t)n * kD + d] = acc / rs;
}

// ---------------------------------------------------------------------------
// Generic GEMM: C[M,NC] = A[M,K] @ B  (B row-major [K,NC], or transB: B[NC,K])
// block = NC threads, RB=16 rows per block
// ---------------------------------------------------------------------------
__global__ void gemm_rb16(const float* __restrict__ A, const float* __restrict__ B,
                          float* __restrict__ C, int M, int K, int NC, int transB) {
    extern __shared__ float a_sh[];     // 16*K
    int r0 = blockIdx.x * 16;
    int e = threadIdx.x;
    for (int idx = threadIdx.x; idx < 16 * K; idx += blockDim.x) {
        int r = idx / K, c = idx - r * K;
        a_sh[idx] = (r0 + r < M) ? A[(size_t)(r0 + r) * K + c] : 0.f;
    }
    __syncthreads();
    float acc[16];
    #pragma unroll
    for (int r = 0; r < 16; r++) acc[r] = 0.f;
    for (int d = 0; d < K; ++d) {
        float bv = transB ? B[(size_t)e * K + d] : B[(size_t)d * NC + e];
        const float* ap = a_sh + d;
        #pragma unroll
        for (int r = 0; r < 16; r++) acc[r] = fmaf(ap[r * K], bv, acc[r]);
    }
    #pragma unroll
    for (int r = 0; r < 16; r++) {
        int row = r0 + r;
        if (row < M) C[(size_t)row * NC + e] = acc[r];
    }
}

// ---------------------------------------------------------------------------
// GAT: es/ed dots
// es/ed layout: es[h*kN + n]
// ---------------------------------------------------------------------------
__global__ void compute_esed(const float* __restrict__ H0, const float* __restrict__ H1,
                             const float* __restrict__ asrc, const float* __restrict__ adst,
                             float* __restrict__ es, float* __restrict__ ed) {
    int n = blockIdx.x, d = threadIdx.x;
    float h0 = H0[(size_t)n * kD + d];
    float h1 = H1[(size_t)n * kD + d];
    float v;
    v = brsum128(h0 * asrc[d]);        if (d == 0) es[n] = v;
    v = brsum128(h1 * asrc[kD + d]);   if (d == 0) es[kN + n] = v;
    v = brsum128(h0 * adst[d]);        if (d == 0) ed[n] = v;
    v = brsum128(h1 * adst[kD + d]);   if (d == 0) ed[kN + n] = v;
}

// ---------------------------------------------------------------------------
// GAT attention aggregation + head mean + elu + row-normalize
// ---------------------------------------------------------------------------
__global__ void gat_attn(const float* __restrict__ H0, const float* __restrict__ H1,
                         const float* __restrict__ es, const float* __restrict__ ed,
                         const int* __restrict__ rowptr, const int* __restrict__ cols,
                         float* __restrict__ hout) {
    int n = blockIdx.x, tid = threadIdx.x;
    int s = rowptr[n], e2 = rowptr[n + 1];
    float acc = 0.f;
    #pragma unroll
    for (int h = 0; h < 2; h++) {
        const float* Hh = h ? H1 : H0;
        const float* edh = ed + h * kN;
        float esn = es[h * kN + n];
        // pass 1: max
        float mx = -1e30f;
        for (int j = s + tid; j < e2; j += 128) {
            float z = esn + edh[cols[j]];
            z = z > 0.f ? z : 0.2f * z;
            mx = fmaxf(mx, z);
        }
        mx = brmax128(mx);
        // pass 2: sum exp
        float se = 0.f;
        for (int j = s + tid; j < e2; j += 128) {
            float z = esn + edh[cols[j]];
            z = z > 0.f ? z : 0.2f * z;
            se += expf(z - mx);
        }
        se = brsum128(se);
        // pass 3: weighted aggregation (thread = feature dim)
        float a = 0.f;
        for (int j = s; j < e2; j++) {
            int m = cols[j];
            float z = esn + edh[m];
            z = z > 0.f ? z : 0.2f * z;
            float w = expf(z - mx) / se;
            a += w * Hh[(size_t)m * kD + tid];
        }
        acc += a;
    }
    acc *= 0.5f;                                   // mean over 2 heads
    acc = acc > 0.f ? acc : expm1f(acc);           // elu
    float nrm = sqrtf(brsum128(acc * acc));
    hout[(size_t)n * kD + tid] = acc / fmaxf(nrm, 1e-12f);
}

// ---------------------------------------------------------------------------
// Build seq buffer [N,3,128] = [x0, h1, h2]
// ---------------------------------------------------------------------------
__global__ void build_seq(const float* __restrict__ x0, const float* __restrict__ h1,
                          const float* __restrict__ h2, float* __restrict__ seq) {
    int n = blockIdx.x, d = threadIdx.x;
    size_t b = (size_t)n * 3 * kD;
    seq[b + d]            = x0[(size_t)n * kD + d];
    seq[b + kD + d]       = h1[(size_t)n * kD + d];
    seq[b + 2 * kD + d]   = h2[(size_t)n * kD + d];
}

// ---------------------------------------------------------------------------
// Per-node MHA attention core (Q,K,V: [N*3,256]) -> oc [N*3,256]
// ---------------------------------------------------------------------------
__global__ void mha_attn(const float* __restrict__ Q, const float* __restrict__ Kb,
                         const float* __restrict__ V, float* __restrict__ OC) {
    int n = blockIdx.x, tid = threadIdx.x;
    __shared__ float q[3][kHD], k[3][kHD], v[3][kHD];
    __shared__ float att[2][3][3];
    size_t base = (size_t)n * 3 * kHD;
    for (int idx = tid; idx < 3 * kHD; idx += 128) {
        int l = idx / kHD, j = idx - l * kHD;
        q[l][j] = Q[base + (size_t)l * kHD + j];
        k[l][j] = Kb[base + (size_t)l * kHD + j];
        v[l][j] = V[base + (size_t)l * kHD + j];
    }
    __syncthreads();
    int wid = tid >> 5, lane = tid & 31;
    const float scale = 0.08838834764831845f;  // 1/sqrt(128)
    for (int t = wid; t < 18; t += 4) {
        int h = t / 9, l = (t % 9) / 3, m = t % 3;
        float s = 0.f;
        for (int d = lane; d < kD; d += 32) s += q[l][h * kD + d] * k[m][h * kD + d];
        #pragma unroll
        for (int o = 16; o > 0; o >>= 1) s += __shfl_down_sync(0xffffffffu, s, o);
        if (lane == 0) att[h][l][m] = s * scale;
    }
    __syncthreads();
    if (tid < 6) {
        int h = tid / 3, l = tid % 3;
        float m0 = att[h][l][0], m1 = att[h][l][1], m2 = att[h][l][2];
        float mx = fmaxf(m0, fmaxf(m1, m2));
        float e0 = expf(m0 - mx), e1 = expf(m1 - mx), e2 = expf(m2 - mx);
        float ss = e0 + e1 + e2;
        att[h][l][0] = e0 / ss; att[h][l][1] = e1 / ss; att[h][l][2] = e2 / ss;
    }
    __syncthreads();
    int d = tid;  // 0..127
    #pragma unroll
    for (int h = 0; h < 2; h++) {
        #pragma unroll
        for (int l = 0; l < 3; l++) {
            float o = att[h][l][0] * v[0][h * kD + d]
                    + att[h][l][1] * v[1][h * kD + d]
                    + att[h][l][2] * v[2][h * kD + d];
            OC[base + (size_t)l * kHD + h * kD + d] = o;
        }
    }
}

// ---------------------------------------------------------------------------
// MHA epilogue: residual + LayerNorm + mean over L, write main output half
// and the relation-agg half.
// ---------------------------------------------------------------------------
__global__ void mha_epilogue(const float* __restrict__ FCO, const float* __restrict__ seq,
                             const float* __restrict__ g, const float* __restrict__ b,
                             const float* __restrict__ relagg, float* __restrict__ out) {
    int n = blockIdx.x, d = threadIdx.x;
    float accmean = 0.f;
    for (int l = 0; l < 3; l++) {
        size_t idx = ((size_t)n * 3 + l) * kD + d;
        float o = FCO[idx] + seq[idx];
        float mu = brsum128(o) * (1.f / 128.f);
        float c = o - mu;
        float var = brsum128(c * c) * (1.f / 128.f);
        float y = g[d] * c * rsqrtf(var + 1e-6f) + b[d];
        accmean += y;
    }
    out[(size_t)n * 256 + d] = accmean * (1.f / 3.f);
    out[(size_t)n * 256 + kD + d] = relagg[(size_t)n * kD + d];
}

// ---------------------------------------------------------------------------
// Hyperbolic ops
// ---------------------------------------------------------------------------
__global__ void k_expmap0(const float* __restrict__ in, float* __restrict__ out) {
    int n = blockIdx.x, d = threadIdx.x;
    float u = in[(size_t)n * kD + d];
    float nn = fmaxf(sqrtf(brsum128(u * u)), 1e-15f);
    float p = tanhf(nn) * u / nn;
    float pn = fmaxf(sqrtf(brsum128(p * p)), 1e-15f);
    if (pn > MAXN) p *= MAXN / pn;
    out[(size_t)n * kD + d] = p;
}

__global__ void k_logmap0(const float* __restrict__ in, float* __restrict__ out) {
    int n = blockIdx.x, d = threadIdx.x;
    float p = in[(size_t)n * kD + d];
    float nn = fmaxf(sqrtf(brsum128(p * p)), 1e-15f);
    out[(size_t)n * kD + d] = atanhf(fminf(nn, 1.f - 1e-7f)) * p / nn;
}

// bias: bb = proj(expmap0(b)); bb[128] = ||bb||^2
__global__ void k_bias(const float* __restrict__ b, float* __restrict__ bb) {
    int d = threadIdx.x;
    float u = b[d];
    float nn = fmaxf(sqrtf(brsum128(u * u)), 1e-15f);
    float p = tanhf(nn) * u / nn;
    float pn = fmaxf(sqrtf(brsum128(p * p)), 1e-15f);
    if (pn > MAXN) p *= MAXN / pn;
    float y2 = brsum128(p * p);
    bb[d] = p;
    if (d == 0) bb[kD] = y2;
}

// U = logmap0(x)@W.T  ->  out = logmap0( proj(mobius_add(proj(expmap0(U)), bb)) )
__global__ void k_hyplinear(const float* __restrict__ U, const float* __restrict__ bb,
                            float* __restrict__ out) {
    int n = blockIdx.x, d = threadIdx.x;
    float u = U[(size_t)n * kD + d];
    float nn = fmaxf(sqrtf(brsum128(u * u)), 1e-15f);
    float x = tanhf(nn) * u / nn;
    float xn = fmaxf(sqrtf(brsum128(x * x)), 1e-15f);
    if (xn > MAXN) x *= MAXN / xn;
    float y = bb[d];
    float y2 = bb[kD];
    float x2 = brsum128(x * x);
    float xy = brsum128(x * y);
    float num = (1.f + 2.f * xy + y2) * x + (1.f - x2) * y;
    float den = fmaxf(1.f + 2.f * xy + x2 * y2, 1e-15f);
    float h = num / den;
    float hn = fmaxf(sqrtf(brsum128(h * h)), 1e-15f);
    if (hn > MAXN) h *= MAXN / hn;
    float hn2 = fmaxf(sqrtf(brsum128(h * h)), 1e-15f);
    out[(size_t)n * kD + d] = atanhf(fminf(hn2, 1.f - 1e-7f)) * h / hn2;
}

// sparse aggregation: Y[n] = sum_j vals[j]*X[cols[j]]
__global__ void spmm(const int* __restrict__ rowptr, const int* __restrict__ cols,
                     const float* __restrict__ vals, const float* __restrict__ X,
                     float* __restrict__ Y) {
    int n = blockIdx.x, d = threadIdx.x;
    float acc = 0.f;
    int e = rowptr[n + 1];
    for (int j = rowptr[n]; j < e; j++)
        acc += vals[j] * X[(size_t)cols[j] * kD + d];
    Y[(size_t)n * kD + d] = acc;
}

// h = proj(expmap0(relu(logmap0(proj(expmap0(agg))))))
__global__ void k_hypact(const float* __restrict__ A, float* __restrict__ Hout) {
    int n = blockIdx.x, d = threadIdx.x;
    float u = A[(size_t)n * kD + d];
    float nn = fmaxf(sqrtf(brsum128(u * u)), 1e-15f);
    float x = tanhf(nn) * u / nn;
    float xn = fmaxf(sqrtf(brsum128(x * x)), 1e-15f);
    if (xn > MAXN) x *= MAXN / xn;
    float n2 = fmaxf(sqrtf(brsum128(x * x)), 1e-15f);
    float l = atanhf(fminf(n2, 1.f - 1e-7f)) * x / n2;
    float r = fmaxf(l, 0.f);
    float n3 = fmaxf(sqrtf(brsum128(r * r)), 1e-15f);
    float y = tanhf(n3) * r / n3;
    float yn = fmaxf(sqrtf(brsum128(y * y)), 1e-15f);
    if (yn > MAXN) y *= MAXN / yn;
    Hout[(size_t)n * kD + d] = y;
}

// hs = ent + logmap0(h); write to hyperbolic output region with relagg concat
__global__ void k_finish(const float* __restrict__ HH, const float* __restrict__ ent,
                         const float* __restrict__ relagg, float* __restrict__ out) {
    int n = blockIdx.x, d = threadIdx.x;
    float h = HH[(size_t)n * kD + d];
    float nn = fmaxf(sqrtf(brsum128(h * h)), 1e-15f);
    float val = atanhf(fminf(nn, 1.f - 1e-7f)) * h / nn;
    out[(size_t)n * 256 + d] = ent[(size_t)n * kD + d] + val;
    out[(size_t)n * 256 + kD + d] = relagg[(size_t)n * kD + d];
}

// ---------------------------------------------------------------------------
// Host side
// ---------------------------------------------------------------------------
static inline void gemm(const float* A, const float* B, float* C,
                        int M, int K, int NC, int transB) {
    gemm_rb16<<<(M + 15) / 16, NC, 16 * K * sizeof(float)>>>(A, B, C, M, K, NC, transB);
}

extern "C" void kernel_launch(void* const* d_in, const int* in_sizes, int n_in,
                              void* d_out, int out_size) {
    (void)in_sizes; (void)n_in; (void)out_size;
    const float* ent_sr     = (const float*)d_in[0];
    const float* ent_tg     = (const float*)d_in[1];
    const float* rel_sr     = (const float*)d_in[2];
    const float* rel_tg     = (const float*)d_in[3];
    const float* adj_sr     = (const float*)d_in[4];
    const float* adj_tg     = (const float*)d_in[5];
    const float* rel_adj_sr = (const float*)d_in[6];
    const float* rel_adj_tg = (const float*)d_in[7];
    const float* gat_W      = (const float*)d_in[8];
    const float* gat_a_src  = (const float*)d_in[9];
    const float* gat_a_dst  = (const float*)d_in[10];
    const float* Wq         = (const float*)d_in[11];
    const float* Wk         = (const float*)d_in[12];
    const float* Wv         = (const float*)d_in[13];
    const float* Wfc        = (const float*)d_in[14];
    const float* ln_g       = (const float*)d_in[15];
    const float* ln_b       = (const float*)d_in[16];
    const float* hgc_W      = (const float*)d_in[17];
    const float* hgc_b      = (const float*)d_in[18];
    float* out = (float*)d_out;

    float* FP; int* IP;
    cudaGetSymbolAddress((void**)&FP, g_fpool);
    cudaGetSymbolAddress((void**)&IP, g_ipool);

    float* relagg0 = FP + 0;
    float* relagg1 = FP + 768000;
    float* H0  = FP + 1536000;
    float* H1  = FP + 2304000;
    float* h1b = FP + 3072000;
    float* h2b = FP + 3840000;
    float* es  = FP + 4608000;
    float* ed  = FP + 4620000;
    float* seq = FP + 4632000;
    float* qb  = FP + 6936000;
    float* kb  = FP + 11544000;
    float* vb  = FP + 16152000;
    float* oc  = FP + 20760000;
    float* fco = FP + 25368000;
    float* t1  = FP + 27672000;
    float* t2  = FP + 28440000;
    float* hh  = FP + 29208000;
    float* bb  = FP + 29976000;
    float* vals0 = FP + 30000000;
    float* vals1 = FP + 31500000;

    int* rowptr0 = IP + 0;
    int* rowptr1 = IP + 6001;
    int* cnt     = IP + 12002;
    int* cols0   = IP + 18002;
    int* cols1   = IP + 18002 + CAP;

    // ---- CSR build for both adjacencies ----
    csr_count<<<kN, 128>>>(adj_sr, cnt);
    scan6000<<<1, 1024>>>(cnt, rowptr0);
    csr_fill<<<kN, 128>>>(adj_sr, rowptr0, cols0, vals0);
    csr_count<<<kN, 128>>>(adj_tg, cnt);
    scan6000<<<1, 1024>>>(cnt, rowptr1);
    csr_fill<<<kN, 128>>>(adj_tg, rowptr1, cols1, vals1);

    // ---- Relation aggregators ----
    rel_agg_kernel<<<kN, 128>>>(rel_adj_sr, rel_sr, relagg0);
    rel_agg_kernel<<<kN, 128>>>(rel_adj_tg, rel_tg, relagg1);

    const int DD = kD * kD;

    for (int br = 0; br < 2; br++) {
        const float* ent    = br ? ent_tg : ent_sr;
        const int*   rowptr = br ? rowptr1 : rowptr0;
        const int*   cols   = br ? cols1 : cols0;
        const float* vals   = br ? vals1 : vals0;
        const float* relagg = br ? relagg1 : relagg0;
        float* out_main = out + (size_t)br * kN * 256;            // region 0 / 1
        float* out_hyp  = out + (size_t)(2 + br) * kN * 256;      // region 2 / 3

        // ---- GAT layer 0 (input = ent) ----
        gemm(ent, gat_W + 0 * DD, H0, kN, kD, kD, 0);
        gemm(ent, gat_W + 1 * DD, H1, kN, kD, kD, 0);
        compute_esed<<<kN, 128>>>(H0, H1, gat_a_src + 0, gat_a_dst + 0, es, ed);
        gat_attn<<<kN, 128>>>(H0, H1, es, ed, rowptr, cols, h1b);

        // ---- GAT layer 1 (input = h1) ----
        gemm(h1b, gat_W + 2 * DD, H0, kN, kD, kD, 0);
        gemm(h1b, gat_W + 3 * DD, H1, kN, kD, kD, 0);
        compute_esed<<<kN, 128>>>(H0, H1, gat_a_src + 2 * kD, gat_a_dst + 2 * kD, es, ed);
        gat_attn<<<kN, 128>>>(H0, H1, es, ed, rowptr, cols, h2b);

        // ---- Multi-range fusion (MHA over [x0,h1,h2]) ----
        build_seq<<<kN, 128>>>(ent, h1b, h2b, seq);
        gemm(seq, Wq, qb, kN * 3, kD, kHD, 0);
        gemm(seq, Wk, kb, kN * 3, kD, kHD, 0);
        gemm(seq, Wv, vb, kN * 3, kD, kHD, 0);
        mha_attn<<<kN, 128>>>(qb, kb, vb, oc);
        gemm(oc, Wfc, fco, kN * 3, kHD, kD, 0);
        mha_epilogue<<<kN, 128>>>(fco, seq, ln_g, ln_b, relagg, out_main);

        // ---- Hyperbolic encoder ----
        k_expmap0<<<kN, 128>>>(ent, hh);
        for (int i = 0; i < 2; i++) {
            k_bias<<<1, 128>>>(hgc_b + i * kD, bb);
            k_logmap0<<<kN, 128>>>(hh, t1);
            gemm(t1, hgc_W + i * DD, t2, kN, kD, kD, 1);      // x @ W.T
            k_hyplinear<<<kN, 128>>>(t2, bb, t1);              // -> logmap0(h)
            spmm<<<kN, 128>>>(rowptr, cols, vals, t1, t2);     // adj @ .
            k_hypact<<<kN, 128>>>(t2, hh);
        }
        k_finish<<<kN, 128>>>(hh, ent, relagg, out_hyp);
    }
}

// round 2
// speedup vs baseline: 2.0337x; 2.0337x over previous
#include <cuda_runtime.h>
#include <cuda_bf16.h>
#include <math.h>
#include <stdint.h>

// ---------------------------------------------------------------------------
// Problem constants
// ---------------------------------------------------------------------------
#define kN   6000
#define kD   128
#define kR   1000
#define MAXN 0.996f        // 1 - 4e-3
#define DD   (128*128)

// ---------------------------------------------------------------------------
// Static scratch pools
// ---------------------------------------------------------------------------
// float pool offsets (elements):
#define OF_RELAGG  0            // 2 x 768000
#define OF_HC      1536000      // 2 x 1536000  ([br][n][256])
#define OF_H1B     4608000      // 2 x 768000
#define OF_H2B     6144000      // 2 x 768000
#define OF_ES      7680000      // 24000  ([br*2+h]*6000)
#define OF_ED      7704000      // 24000
#define OF_SEQ     7728000      // 4608000  ([br*6000+n]*3*128)
#define OF_QB      12336000     // 9216000
#define OF_KB      21552000     // 9216000
#define OF_VB      30768000     // 9216000
#define OF_OC      39984000     // 9216000
#define OF_FCO     49200000     // 4608000
#define OF_T1      53808000     // 1536000
#define OF_T2      55344000     // 1536000
#define OF_HH      56880000     // 1536000
#define OF_BB      58416000     // 129
#define OF_VALS    58420000     // 1536000  ([br*6000+n]*128)
__device__ float g_fpool[60000000];

#define IO_COLS 0               // 1536000
#define IO_CNT  1536000         // 12000
__device__ int g_ipool[1549000];

// ---------------------------------------------------------------------------
// Block reductions (blockDim.x == 128)
// ---------------------------------------------------------------------------
__device__ __forceinline__ float brsum128(float v) {
    __shared__ float sh[4];
    #pragma unroll
    for (int o = 16; o > 0; o >>= 1) v += __shfl_down_sync(0xffffffffu, v, o);
    __syncthreads();
    if ((threadIdx.x & 31) == 0) sh[threadIdx.x >> 5] = v;
    __syncthreads();
    return sh[0] + sh[1] + sh[2] + sh[3];
}

__device__ __forceinline__ float brmax128(float v) {
    __shared__ float shm[4];
    #pragma unroll
    for (int o = 16; o > 0; o >>= 1) v = fmaxf(v, __shfl_down_sync(0xffffffffu, v, o));
    __syncthreads();
    if ((threadIdx.x & 31) == 0) shm[threadIdx.x >> 5] = v;
    __syncthreads();
    return fmaxf(fmaxf(shm[0], shm[1]), fmaxf(shm[2], shm[3]));
}

// ---------------------------------------------------------------------------
// ELL adjacency build (single pass; cap 128 nnz/row, true nnz ~32 +- 6)
// ---------------------------------------------------------------------------
__global__ void ell_build(const float* __restrict__ adj0, const float* __restrict__ adj1,
                          int* __restrict__ cols, float* __restrict__ vals,
                          int* __restrict__ cnt) {
    int br = blockIdx.y, n = blockIdx.x, tid = threadIdx.x;
    const float* row = (br ? adj1 : adj0) + (size_t)n * kN;
    __shared__ int sh[128];
    int c = 0;
    for (int m = tid; m < kN; m += 128) if (row[m] > 0.f) c++;
    sh[tid] = c;
    __syncthreads();
    int off = 0;
    for (int i = 0; i < tid; i++) off += sh[i];
    size_t base = (size_t)(br * kN + n) * 128;
    int pos = off;
    for (int m = tid; m < kN; m += 128) {
        float v = row[m];
        if (v > 0.f) {
            if (pos < 128) { cols[base + pos] = m; vals[base + pos] = v; }
            pos++;
        }
    }
    if (tid == 127) cnt[br * kN + n] = min(off + c, 128);
}

// ---------------------------------------------------------------------------
// Relation aggregator (shared-chunked)
// ---------------------------------------------------------------------------
__global__ void rel_agg_kernel(const float* __restrict__ ra0, const float* __restrict__ ra1,
                               const float* __restrict__ rel0, const float* __restrict__ rel1,
                               float* __restrict__ outp) {
    int br = blockIdx.y, n = blockIdx.x, d = threadIdx.x;
    const float* row = (br ? ra1 : ra0) + (size_t)n * kR;
    const float* rel = br ? rel1 : rel0;
    __shared__ float sh[128];
    float acc = 0.f, rs = 0.f;
    for (int r0 = 0; r0 < kR; r0 += 128) {
        int r = r0 + d;
        sh[d] = (r < kR) ? row[r] : 0.f;
        __syncthreads();
        int lim = min(128, kR - r0);
        for (int j = 0; j < lim; j++) {
            float v = sh[j];
            if (v != 0.f) { rs += v; acc += v * rel[(size_t)(r0 + j) * kD + d]; }
        }
        __syncthreads();
    }
    outp[((size_t)br * kN + n) * kD + d] = acc / rs;
}

// ---------------------------------------------------------------------------
// Tiled GEMM: C[M,NC] = A[M,K] @ B
//  mode 0: B row-major [K, ldb]  (seg>0: two stacked head matrices, each [128,128])
//  mode 2: transB, B [NC, ldb=K] row-major (C = A @ B^T)
//  BM=128 BN=64 BK=32, 128 threads, 8x8 register tile
//  blockIdx.z selects (A,B,C) triple.
// ---------------------------------------------------------------------------
__global__ __launch_bounds__(128)
void gemm_tiled(const float* __restrict__ A0, const float* __restrict__ A1, const float* __restrict__ A2,
                const float* __restrict__ B0, const float* __restrict__ B1, const float* __restrict__ B2,
                float* __restrict__ C0, float* __restrict__ C1, float* __restrict__ C2,
                int M, int K, int ldb, int ldc, int mode, int seg) {
    __shared__ float As[32][132];
    __shared__ float Bs[32][68];
    const float* A = blockIdx.z == 0 ? A0 : (blockIdx.z == 1 ? A1 : A2);
    const float* B = blockIdx.z == 0 ? B0 : (blockIdx.z == 1 ? B1 : B2);
    float* C       = blockIdx.z == 0 ? C0 : (blockIdx.z == 1 ? C1 : C2);
    int m0 = blockIdx.x * 128, n0 = blockIdx.y * 64;
    int tid = threadIdx.x;
    int tx = tid & 7, ty = tid >> 3;
    const float* Bp; int bcol0;
    if (mode == 0 && seg > 0) { Bp = B + (size_t)(n0 >> 7) * seg; bcol0 = n0 & 127; }
    else { Bp = B; bcol0 = n0; }

    float acc[8][8];
    #pragma unroll
    for (int i = 0; i < 8; i++)
        #pragma unroll
        for (int j = 0; j < 8; j++) acc[i][j] = 0.f;

    for (int k0 = 0; k0 < K; k0 += 32) {
        // A tile: 128 rows x 32 -> transposed into As[k][m]
        #pragma unroll
        for (int i = 0; i < 8; i++) {
            int idx = i * 128 + tid;
            int r = idx >> 3, c = idx & 7;
            int gr = m0 + r;
            float4 v = make_float4(0.f, 0.f, 0.f, 0.f);
            if (gr < M) v = *(const float4*)(A + (size_t)gr * K + k0 + 4 * c);
            As[4 * c + 0][r] = v.x; As[4 * c + 1][r] = v.y;
            As[4 * c + 2][r] = v.z; As[4 * c + 3][r] = v.w;
        }
        // B tile
        if (mode == 0) {
            #pragma unroll
            for (int i = 0; i < 4; i++) {
                int idx = i * 128 + tid;
                int k = idx >> 4, c = idx & 15;
                float4 v = *(const float4*)(Bp + (size_t)(k0 + k) * ldb + bcol0 + 4 * c);
                Bs[k][4 * c + 0] = v.x; Bs[k][4 * c + 1] = v.y;
                Bs[k][4 * c + 2] = v.z; Bs[k][4 * c + 3] = v.w;
            }
        } else {
            #pragma unroll
            for (int i = 0; i < 4; i++) {
                int idx = i * 128 + tid;
                int n = idx >> 3, c = idx & 7;
                float4 v = *(const float4*)(Bp + (size_t)(bcol0 + n) * ldb + k0 + 4 * c);
                Bs[4 * c + 0][n] = v.x; Bs[4 * c + 1][n] = v.y;
                Bs[4 * c + 2][n] = v.z; Bs[4 * c + 3][n] = v.w;
            }
        }
        __syncthreads();
        #pragma unroll
        for (int k = 0; k < 32; k++) {
            float a[8], b[8];
            *(float4*)&a[0] = *(const float4*)&As[k][ty * 8];
            *(float4*)&a[4] = *(const float4*)&As[k][ty * 8 + 4];
            *(float4*)&b[0] = *(const float4*)&Bs[k][tx * 8];
            *(float4*)&b[4] = *(const float4*)&Bs[k][tx * 8 + 4];
            #pragma unroll
            for (int i = 0; i < 8; i++)
                #pragma unroll
                for (int j = 0; j < 8; j++)
                    acc[i][j] = fmaf(a[i], b[j], acc[i][j]);
        }
        __syncthreads();
    }
    #pragma unroll
    for (int i = 0; i < 8; i++) {
        int gr = m0 + ty * 8 + i;
        if (gr < M) {
            #pragma unroll
            for (int j = 0; j < 8; j += 4) {
                float4 v = make_float4(acc[i][j], acc[i][j + 1], acc[i][j + 2], acc[i][j + 3]);
                *(float4*)(C + (size_t)gr * ldc + n0 + tx * 8 + j) = v;
            }
        }
    }
}

// ---------------------------------------------------------------------------
// GAT attention scores es/ed; Hc layout [br][n][256]
// ---------------------------------------------------------------------------
__global__ void compute_esed(const float* __restrict__ Hc, const float* __restrict__ asrc,
                             const float* __restrict__ adst,
                             float* __restrict__ es, float* __restrict__ ed) {
    int br = blockIdx.y, n = blockIdx.x, d = threadIdx.x;
    const float* hrow = Hc + ((size_t)br * kN + n) * 256;
    float h0 = hrow[d], h1 = hrow[128 + d];
    float v;
    v = brsum128(h0 * asrc[d]);        if (d == 0) es[(br * 2 + 0) * kN + n] = v;
    v = brsum128(h1 * asrc[128 + d]);  if (d == 0) es[(br * 2 + 1) * kN + n] = v;
    v = brsum128(h0 * adst[d]);        if (d == 0) ed[(br * 2 + 0) * kN + n] = v;
    v = brsum128(h1 * adst[128 + d]);  if (d == 0) ed[(br * 2 + 1) * kN + n] = v;
}

// ---------------------------------------------------------------------------
// GAT attention aggregation + head mean + elu + normalize
// ---------------------------------------------------------------------------
__global__ void gat_attn(const float* __restrict__ Hc, const float* __restrict__ es,
                         const float* __restrict__ ed, const int* __restrict__ cols,
                         const int* __restrict__ cnt, float* __restrict__ hout) {
    int br = blockIdx.y, n = blockIdx.x, tid = threadIdx.x;
    int c = cnt[br * kN + n];
    size_t base = (size_t)(br * kN + n) * 128;
    __shared__ int csh[128];
    __shared__ float wsh[2][128];
    if (tid < c) csh[tid] = cols[base + tid];
    __syncthreads();
    #pragma unroll
    for (int h = 0; h < 2; h++) {
        float esn = es[(br * 2 + h) * kN + n];
        const float* edh = ed + (size_t)(br * 2 + h) * kN;
        float z = -1e30f;
        if (tid < c) {
            z = esn + edh[csh[tid]];
            z = z > 0.f ? z : 0.2f * z;
        }
        float mx = brmax128(z);
        float ex = (tid < c) ? expf(z - mx) : 0.f;
        float se = brsum128(ex);
        if (tid < c) wsh[h][tid] = ex / se;
    }
    __syncthreads();
    const float* Hb = Hc + (size_t)br * kN * 256;
    float a0 = 0.f, a1 = 0.f;
    for (int j = 0; j < c; j++) {
        size_t ro = (size_t)csh[j] * 256 + tid;
        a0 += wsh[0][j] * Hb[ro];
        a1 += wsh[1][j] * Hb[ro + 128];
    }
    float acc = 0.5f * (a0 + a1);
    acc = acc > 0.f ? acc : expm1f(acc);           // elu
    float nrm = sqrtf(brsum128(acc * acc));
    hout[base + tid] = acc / fmaxf(nrm, 1e-12f);
}

// ---------------------------------------------------------------------------
// seq = stack([x0, h1, h2], axis=1)
// ---------------------------------------------------------------------------
__global__ void build_seq(const float* __restrict__ e0, const float* __restrict__ e1,
                          const float* __restrict__ h1b, const float* __restrict__ h2b,
                          float* __restrict__ seq) {
    int br = blockIdx.y, n = blockIdx.x, d = threadIdx.x;
    size_t rb = (size_t)br * kN + n;
    size_t b = rb * 3 * 128;
    const float* ent = br ? e1 : e0;
    seq[b + d]           = ent[(size_t)n * 128 + d];
    seq[b + 128 + d]     = h1b[rb * 128 + d];
    seq[b + 256 + d]     = h2b[rb * 128 + d];
}

// ---------------------------------------------------------------------------
// Per-node MHA (L=3, H=2, D=128)
// ---------------------------------------------------------------------------
__global__ void mha_attn(const float* __restrict__ Q, const float* __restrict__ Kb,
                         const float* __restrict__ V, float* __restrict__ OC) {
    int n = blockIdx.x, tid = threadIdx.x;
    __shared__ float q[3][256], k[3][256], v[3][256];
    __shared__ float att[2][3][3];
    size_t base = (size_t)n * 3 * 256;
    for (int idx = tid; idx < 768; idx += 128) {
        int l = idx >> 8, j = idx & 255;
        q[l][j] = Q[base + (size_t)l * 256 + j];
        k[l][j] = Kb[base + (size_t)l * 256 + j];
        v[l][j] = V[base + (size_t)l * 256 + j];
    }
    __syncthreads();
    int wid = tid >> 5, lane = tid & 31;
    const float scale = 0.08838834764831845f;  // 1/sqrt(128)
    for (int t = wid; t < 18; t += 4) {
        int h = t / 9, l = (t % 9) / 3, m = t % 3;
        float s = 0.f;
        for (int d = lane; d < 128; d += 32) s += q[l][h * 128 + d] * k[m][h * 128 + d];
        #pragma unroll
        for (int o = 16; o > 0; o >>= 1) s += __shfl_down_sync(0xffffffffu, s, o);
        if (lane == 0) att[h][l][m] = s * scale;
    }
    __syncthreads();
    if (tid < 6) {
        int h = tid / 3, l = tid % 3;
        float m0 = att[h][l][0], m1 = att[h][l][1], m2 = att[h][l][2];
        float mx = fmaxf(m0, fmaxf(m1, m2));
        float e0 = expf(m0 - mx), e1 = expf(m1 - mx), e2 = expf(m2 - mx);
        float ss = e0 + e1 + e2;
        att[h][l][0] = e0 / ss; att[h][l][1] = e1 / ss; att[h][l][2] = e2 / ss;
    }
    __syncthreads();
    int d = tid;
    #pragma unroll
    for (int h = 0; h < 2; h++) {
        #pragma unroll
        for (int l = 0; l < 3; l++) {
            float o = att[h][l][0] * v[0][h * 128 + d]
                    + att[h][l][1] * v[1][h * 128 + d]
                    + att[h][l][2] * v[2][h * 128 + d];
            OC[base + (size_t)l * 256 + h * 128 + d] = o;
        }
    }
}

// ---------------------------------------------------------------------------
// MHA epilogue: residual + LN + mean over L; write out[.., 0:128] and relagg half
// ---------------------------------------------------------------------------
__global__ void mha_epilogue(const float* __restrict__ FCO, const float* __restrict__ seq,
                             const float* __restrict__ g, const float* __restrict__ b,
                             const float* __restrict__ relagg, float* __restrict__ out) {
    int br = blockIdx.y, n = blockIdx.x, d = threadIdx.x;
    size_t rb = (size_t)br * kN + n;
    float accmean = 0.f;
    for (int l = 0; l < 3; l++) {
        size_t idx = (rb * 3 + l) * 128 + d;
        float o = FCO[idx] + seq[idx];
        float mu = brsum128(o) * (1.f / 128.f);
        float c = o - mu;
        float var = brsum128(c * c) * (1.f / 128.f);
        accmean += g[d] * c * rsqrtf(var + 1e-6f) + b[d];
    }
    float* ob = out + (size_t)br * kN * 256;
    ob[(size_t)n * 256 + d] = accmean * (1.f / 3.f);
    ob[(size_t)n * 256 + 128 + d] = relagg[rb * 128 + d];
}

// ---------------------------------------------------------------------------
// Hyperbolic ops
// ---------------------------------------------------------------------------
__global__ void k_expmap0(const float* __restrict__ e0, const float* __restrict__ e1,
                          float* __restrict__ outp) {
    int br = blockIdx.y, n = blockIdx.x, d = threadIdx.x;
    const float* in = br ? e1 : e0;
    float u = in[(size_t)n * 128 + d];
    float nn = fmaxf(sqrtf(brsum128(u * u)), 1e-15f);
    float p = tanhf(nn) * u / nn;
    float pn = fmaxf(sqrtf(brsum128(p * p)), 1e-15f);
    if (pn > MAXN) p *= MAXN / pn;
    outp[((size_t)br * kN + n) * 128 + d] = p;
}

__global__ void k_logmap0(const float* __restrict__ in, float* __restrict__ outp) {
    int n = blockIdx.x, d = threadIdx.x;
    float p = in[(size_t)n * 128 + d];
    float nn = fmaxf(sqrtf(brsum128(p * p)), 1e-15f);
    outp[(size_t)n * 128 + d] = atanhf(fminf(nn, 1.f - 1e-7f)) * p / nn;
}

__global__ void k_bias(const float* __restrict__ b, float* __restrict__ bb) {
    int d = threadIdx.x;
    float u = b[d];
    float nn = fmaxf(sqrtf(brsum128(u * u)), 1e-15f);
    float p = tanhf(nn) * u / nn;
    float pn = fmaxf(sqrtf(brsum128(p * p)), 1e-15f);
    if (pn > MAXN) p *= MAXN / pn;
    float y2 = brsum128(p * p);
    bb[d] = p;
    if (d == 0) bb[128] = y2;
}

__global__ void k_hyplinear(const float* __restrict__ U, const float* __restrict__ bb,
                            float* __restrict__ outp) {
    int n = blockIdx.x, d = threadIdx.x;
    float u = U[(size_t)n * 128 + d];
    float nn = fmaxf(sqrtf(brsum128(u * u)), 1e-15f);
    float x = tanhf(nn) * u / nn;
    float xn = fmaxf(sqrtf(brsum128(x * x)), 1e-15f);
    if (xn > MAXN) x *= MAXN / xn;
    float y = bb[d];
    float y2 = bb[128];
    float x2 = brsum128(x * x);
    float xy = brsum128(x * y);
    float num = (1.f + 2.f * xy + y2) * x + (1.f - x2) * y;
    float den = fmaxf(1.f + 2.f * xy + x2 * y2, 1e-15f);
    float h = num / den;
    float hn = fmaxf(sqrtf(brsum128(h * h)), 1e-15f);
    if (hn > MAXN) h *= MAXN / hn;
    float hn2 = fmaxf(sqrtf(brsum128(h * h)), 1e-15f);
    outp[(size_t)n * 128 + d] = atanhf(fminf(hn2, 1.f - 1e-7f)) * h / hn2;
}

__global__ void spmm(const int* __restrict__ cols, const float* __restrict__ vals,
                     const int* __restrict__ cnt, const float* __restrict__ X,
                     float* __restrict__ Y) {
    int br = blockIdx.y, n = blockIdx.x, tid = threadIdx.x;
    int c = cnt[br * kN + n];
    size_t base = (size_t)(br * kN + n) * 128;
    __shared__ int csh[128];
    __shared__ float vsh[128];
    if (tid < c) { csh[tid] = cols[base + tid]; vsh[tid] = vals[base + tid]; }
    __syncthreads();
    const float* Xb = X + (size_t)br * kN * 128;
    float acc = 0.f;
    for (int j = 0; j < c; j++)
        acc += vsh[j] * Xb[(size_t)csh[j] * 128 + tid];
    Y[base + tid] = acc;
}

__global__ void k_hypact(const float* __restrict__ A, float* __restrict__ Hout) {
    int n = blockIdx.x, d = threadIdx.x;
    float u = A[(size_t)n * 128 + d];
    float nn = fmaxf(sqrtf(brsum128(u * u)), 1e-15f);
    float x = tanhf(nn) * u / nn;
    float xn = fmaxf(sqrtf(brsum128(x * x)), 1e-15f);
    if (xn > MAXN) x *= MAXN / xn;
    float n2 = fmaxf(sqrtf(brsum128(x * x)), 1e-15f);
    float l = atanhf(fminf(n2, 1.f - 1e-7f)) * x / n2;
    float r = fmaxf(l, 0.f);
    float n3 = fmaxf(sqrtf(brsum128(r * r)), 1e-15f);
    float y = tanhf(n3) * r / n3;
    float yn = fmaxf(sqrtf(brsum128(y * y)), 1e-15f);
    if (yn > MAXN) y *= MAXN / yn;
    Hout[(size_t)n * 128 + d] = y;
}

__global__ void k_finish(const float* __restrict__ HH, const float* __restrict__ e0,
                         const float* __restrict__ e1, const float* __restrict__ relagg,
                         float* __restrict__ out) {
    int br = blockIdx.y, n = blockIdx.x, d = threadIdx.x;
    size_t rb = (size_t)br * kN + n;
    float h = HH[rb * 128 + d];
    float nn = fmaxf(sqrtf(brsum128(h * h)), 1e-15f);
    float val = atanhf(fminf(nn, 1.f - 1e-7f)) * h / nn;
    const float* ent = br ? e1 : e0;
    float* ob = out + (size_t)(2 + br) * kN * 256;
    ob[(size_t)n * 256 + d] = ent[(size_t)n * 128 + d] + val;
    ob[(size_t)n * 256 + 128 + d] = relagg[rb * 128 + d];
}

// ---------------------------------------------------------------------------
// Host side
// ---------------------------------------------------------------------------
extern "C" void kernel_launch(void* const* d_in, const int* in_sizes, int n_in,
                              void* d_out, int out_size) {
    (void)in_sizes; (void)n_in; (void)out_size;
    const float* ent_sr     = (const float*)d_in[0];
    const float* ent_tg     = (const float*)d_in[1];
    const float* rel_sr     = (const float*)d_in[2];
    const float* rel_tg     = (const float*)d_in[3];
    const float* adj_sr     = (const float*)d_in[4];
    const float* adj_tg     = (const float*)d_in[5];
    const float* rel_adj_sr = (const float*)d_in[6];
    const float* rel_adj_tg = (const float*)d_in[7];
    const float* gat_W      = (const float*)d_in[8];
    const float* gat_a_src  = (const float*)d_in[9];
    const float* gat_a_dst  = (const float*)d_in[10];
    const float* Wq         = (const float*)d_in[11];
    const float* Wk         = (const float*)d_in[12];
    const float* Wv         = (const float*)d_in[13];
    const float* Wfc        = (const float*)d_in[14];
    const float* ln_g       = (const float*)d_in[15];
    const float* ln_b       = (const float*)d_in[16];
    const float* hgc_W      = (const float*)d_in[17];
    const float* hgc_b      = (const float*)d_in[18];
    float* out = (float*)d_out;

    float* FP; int* IP;
    cudaGetSymbolAddress((void**)&FP, g_fpool);
    cudaGetSymbolAddress((void**)&IP, g_ipool);

    float* relagg = FP + OF_RELAGG;
    float* Hc   = FP + OF_HC;
    float* h1b  = FP + OF_H1B;
    float* h2b  = FP + OF_H2B;
    float* es   = FP + OF_ES;
    float* ed   = FP + OF_ED;
    float* seq  = FP + OF_SEQ;
    float* qb   = FP + OF_QB;
    float* kb   = FP + OF_KB;
    float* vb   = FP + OF_VB;
    float* oc   = FP + OF_OC;
    float* fco  = FP + OF_FCO;
    float* t1   = FP + OF_T1;
    float* t2   = FP + OF_T2;
    float* hh   = FP + OF_HH;
    float* bb   = FP + OF_BB;
    float* vals = FP + OF_VALS;
    int* cols = IP + IO_COLS;
    int* cnt  = IP + IO_CNT;

    dim3 gN2(kN, 2);

    // ELL adjacency + relation aggregators
    ell_build<<<gN2, 128>>>(adj_sr, adj_tg, cols, vals, cnt);
    rel_agg_kernel<<<gN2, 128>>>(rel_adj_sr, rel_adj_tg, rel_sr, rel_tg, relagg);

    float* Hc0 = Hc;
    float* Hc1 = Hc + (size_t)kN * 256;
    float* h1b0 = h1b;
    float* h1b1 = h1b + (size_t)kN * 128;

    // ---- GAT layer 0: both branches, both heads in one launch ----
    gemm_tiled<<<dim3(47, 4, 2), 128>>>(ent_sr, ent_tg, ent_tg,
                                        gat_W, gat_W, gat_W,
                                        Hc0, Hc1, Hc1,
                                        kN, 128, 128, 256, 0, DD);
    compute_esed<<<gN2, 128>>>(Hc, gat_a_src, gat_a_dst, es, ed);
    gat_attn<<<gN2, 128>>>(Hc, es, ed, cols, cnt, h1b);

    // ---- GAT layer 1 ----
    gemm_tiled<<<dim3(47, 4, 2), 128>>>(h1b0, h1b1, h1b1,
                                        gat_W + 2 * DD, gat_W + 2 * DD, gat_W + 2 * DD,
                                        Hc0, Hc1, Hc1,
                                        kN, 128, 128, 256, 0, DD);
    compute_esed<<<gN2, 128>>>(Hc, gat_a_src + 256, gat_a_dst + 256, es, ed);
    gat_attn<<<gN2, 128>>>(Hc, es, ed, cols, cnt, h2b);

    // ---- Multi-range fusion (MHA over [x0,h1,h2]) ----
    build_seq<<<gN2, 128>>>(ent_sr, ent_tg, h1b, h2b, seq);
    gemm_tiled<<<dim3(282, 4, 3), 128>>>(seq, seq, seq, Wq, Wk, Wv, qb, kb, vb,
                                         36000, 128, 256, 256, 0, 0);
    mha_attn<<<12000, 128>>>(qb, kb, vb, oc);
    gemm_tiled<<<dim3(282, 2, 1), 128>>>(oc, oc, oc, Wfc, Wfc, Wfc, fco, fco, fco,
                                         36000, 256, 128, 128, 0, 0);
    mha_epilogue<<<gN2, 128>>>(fco, seq, ln_g, ln_b, relagg, out);

    // ---- Hyperbolic encoder (both branches lockstep, contiguous 12000 rows) ----
    k_expmap0<<<gN2, 128>>>(ent_sr, ent_tg, hh);
    for (int i = 0; i < 2; i++) {
        k_bias<<<1, 128>>>(hgc_b + i * 128, bb);
        k_logmap0<<<12000, 128>>>(hh, t1);
        gemm_tiled<<<dim3(94, 2, 1), 128>>>(t1, t1, t1,
                                            hgc_W + i * DD, hgc_W + i * DD, hgc_W + i * DD,
                                            t2, t2, t2,
                                            12000, 128, 128, 128, 2, 0);   // x @ W.T
        k_hyplinear<<<12000, 128>>>(t2, bb, t1);
        spmm<<<gN2, 128>>>(cols, vals, cnt, t1, t2);
        k_hypact<<<12000, 128>>>(t2, hh);
    }
    k_finish<<<gN2, 128>>>(hh, ent_sr, ent_tg, relagg, out);
}